// round 7
// baseline (speedup 1.0000x reference)
#include <cuda_runtime.h>
#include <cstdint>

// x [4,4096,2048] fp32 -> out fp32. R=64.
#define N_TOK    16384
#define D_DIM    2048
#define R_DIM    64
#define TOK_TILE 64
#define DC       64
#define NCHUNK   (D_DIM / DC)     // 32
#define EPS      1e-5f
#define THREADS  256
#define NSTAGE   3

// dynamic smem (floats): sX[3][64*64] + sW[3][64*64] = 24576 floats = 96 KB
#define SX_OFF(b)   ((b) * 4096)
#define SW_OFF(b)   (12288 + (b) * 4096)
#define SMEM_FLOATS 24576
#define SMEM_BYTES  (SMEM_FLOATS * 4)

__device__ float g_C1[R_DIM];            // sum_d gw[r][d]
__device__ float g_C2[R_DIM];            // sum_d beta*w_down + b_down
__device__ float g_gw[R_DIM * D_DIM];    // tf32(gamma[d] * w_down[r][d])

// ---------------- helpers ----------------

__device__ __forceinline__ float to_tf32(float x) {
    unsigned u;
    asm("cvt.rna.tf32.f32 %0, %1;" : "=r"(u) : "f"(x));
    return __uint_as_float(u);
}
__device__ __forceinline__ int swz4(int row, int c4) { return row * 16 + ((c4 + row) & 15); }
__device__ __forceinline__ int swzf(int row, int col) {
    return (row << 6) + ((((col >> 2) + row) & 15) << 2) + (col & 3);
}
__device__ __forceinline__ void mma_tf32(float* c, const unsigned* a, const unsigned* b) {
    asm volatile(
        "mma.sync.aligned.m16n8k8.row.col.f32.tf32.tf32.f32 "
        "{%0,%1,%2,%3}, {%4,%5,%6,%7}, {%8,%9}, {%0,%1,%2,%3};"
        : "+f"(c[0]), "+f"(c[1]), "+f"(c[2]), "+f"(c[3])
        : "r"(a[0]), "r"(a[1]), "r"(a[2]), "r"(a[3]), "r"(b[0]), "r"(b[1]));
}

#define CPA16(dst_u32, src_ptr) \
    asm volatile("cp.async.cg.shared.global [%0], [%1], 16;" :: "r"(dst_u32), "l"(src_ptr))
#define CPC()  asm volatile("cp.async.commit_group;")
#define CPW2() asm volatile("cp.async.wait_group 2;")
#define CPW1() asm volatile("cp.async.wait_group 1;")
#define CPW0() asm volatile("cp.async.wait_group 0;")

__device__ __forceinline__ void cpw_tail(int c) {
    if (c < NCHUNK - 2)       { CPW2(); }
    else if (c == NCHUNK - 2) { CPW1(); }
    else                      { CPW0(); }
}

// ---------------- prep: gw = tf32(gamma*w_down), C1, C2 ----------------

__global__ void prep_kernel(const float* __restrict__ w_down,
                            const float* __restrict__ gamma,
                            const float* __restrict__ beta,
                            const float* __restrict__ b_down) {
    __shared__ float red1[8], red2[8];
    int r = blockIdx.x;
    float s1 = 0.f, s2 = 0.f;
    for (int d = threadIdx.x; d < D_DIM; d += 256) {
        float w = w_down[r * D_DIM + d];
        float gwv = to_tf32(gamma[d] * w);
        g_gw[r * D_DIM + d] = gwv;
        s1 += gwv;
        s2 += beta[d] * w;
    }
    #pragma unroll
    for (int o = 16; o; o >>= 1) {
        s1 += __shfl_down_sync(0xFFFFFFFFu, s1, o);
        s2 += __shfl_down_sync(0xFFFFFFFFu, s2, o);
    }
    if ((threadIdx.x & 31) == 0) { red1[threadIdx.x >> 5] = s1; red2[threadIdx.x >> 5] = s2; }
    __syncthreads();
    if (threadIdx.x == 0) {
        float t1 = 0.f, t2 = 0.f;
        #pragma unroll
        for (int i = 0; i < 8; i++) { t1 += red1[i]; t2 += red2[i]; }
        g_C1[r] = t1;
        g_C2[r] = t2 + b_down[r];
    }
}

// ---------------- main fused kernel ----------------

__global__ __launch_bounds__(THREADS, 2) void adapter_main(
    const float* __restrict__ x,
    const float* __restrict__ w_up,
    const float* __restrict__ b_up,
    const float* __restrict__ scale,
    float* __restrict__ out)
{
    extern __shared__ float smem[];
    const uint32_t sbase = (uint32_t)__cvta_generic_to_shared(smem);

    const int tid  = threadIdx.x;
    const int lane = tid & 31;
    const int wrp  = tid >> 5;          // 0..7
    const int mg   = wrp & 3;           // 16-token m-strip (0..3)
    const int ng   = wrp >> 2;          // 32-col n-strip (0..1)
    const int t0   = blockIdx.x * TOK_TILE;
    const int tr0  = mg * 16 + (lane >> 2);

    const float scaleV = scale[0];

    const float4* __restrict__ xg  = reinterpret_cast<const float4*>(x) + (size_t)t0 * (D_DIM / 4);
    const float4* __restrict__ gwg = reinterpret_cast<const float4*>(g_gw);
    const float4* __restrict__ wug = reinterpret_cast<const float4*>(w_up);

    // staging coords: x 4 slots/thread, w 4 slots/thread (64 rows x 16 float4 each)
    int xt[4], xc4[4], xdst[4];
    #pragma unroll
    for (int i = 0; i < 4; i++) {
        int idx4 = i * THREADS + tid;
        xt[i] = idx4 >> 4; xc4[i] = idx4 & 15;
        xdst[i] = swz4(xt[i], xc4[i]) * 16;
    }

    float acc[4][4];
    #pragma unroll
    for (int nt = 0; nt < 4; nt++)
        #pragma unroll
        for (int i = 0; i < 4; i++) acc[nt][i] = 0.f;

    float sum4[4], sq4[4];
    #pragma unroll
    for (int i = 0; i < 4; i++) { sum4[i] = 0.f; sq4[i] = 0.f; }

    auto stage1 = [&](int c, int b) {
        const uint32_t xb = sbase + SX_OFF(b) * 4;
        const uint32_t wb = sbase + SW_OFF(b) * 4;
        #pragma unroll
        for (int i = 0; i < 4; i++)
            CPA16(xb + xdst[i], xg + (size_t)xt[i] * (D_DIM / 4) + c * 16 + xc4[i]);
        #pragma unroll
        for (int i = 0; i < 4; i++)
            CPA16(wb + xdst[i], gwg + (size_t)xt[i] * (D_DIM / 4) + c * 16 + xc4[i]);
        CPC();
    };

    // ===================== Pass 1: stats + G = x @ gw^T =====================
    stage1(0, 0); stage1(1, 1); stage1(2, 2);

    for (int c = 0; c < NCHUNK; c++) {
        const int b = c % NSTAGE;
        cpw_tail(c);
        __syncthreads();

        const float*  bX  = smem + SX_OFF(b);
        const float*  bW  = smem + SW_OFF(b);
        const float4* bX4 = reinterpret_cast<const float4*>(bX);

        // stats from the slots this thread staged
        #pragma unroll
        for (int i = 0; i < 4; i++) {
            float4 v = bX4[swz4(xt[i], xc4[i])];
            sum4[i] += v.x + v.y + v.z + v.w;
            sq4[i]  += v.x * v.x + v.y * v.y + v.z * v.z + v.w * v.w;
        }

        #pragma unroll
        for (int ks = 0; ks < 8; ks++) {
            int kb = ks * 8 + (lane & 3);
            unsigned a[4];
            a[0] = __float_as_uint(bX[swzf(tr0,     kb)]);
            a[1] = __float_as_uint(bX[swzf(tr0 + 8, kb)]);
            a[2] = __float_as_uint(bX[swzf(tr0,     kb + 4)]);
            a[3] = __float_as_uint(bX[swzf(tr0 + 8, kb + 4)]);
            #pragma unroll
            for (int nt = 0; nt < 4; nt++) {
                int n = ng * 32 + nt * 8 + (lane >> 2);
                unsigned bb[2];
                bb[0] = __float_as_uint(bW[swzf(n, kb)]);
                bb[1] = __float_as_uint(bW[swzf(n, kb + 4)]);
                mma_tf32(acc[nt], a, bb);
            }
        }
        __syncthreads();
        if (c + NSTAGE < NCHUNK) stage1(c + NSTAGE, b);
    }

    // ===================== stats finalize =====================
    // partials: slot idx4 = i*256+tid -> token = idx4>>4 (0..63), j = idx4&15
    float* sWf = smem + SW_OFF(0);     // scratch: needs 2048+128 floats < 4096
    #pragma unroll
    for (int i = 0; i < 4; i++) {
        int idx4 = i * THREADS + tid;
        sWf[idx4]        = sum4[i];
        sWf[1024 + idx4] = sq4[i];
    }
    __syncthreads();

    float* sMu = sWf + 2048;           // [64] mu, [64] rstd
    if (tid < TOK_TILE) {
        float s = 0.f, q = 0.f;
        #pragma unroll
        for (int j = 0; j < 16; j++) {
            s += sWf[tid * 16 + j];
            q += sWf[1024 + tid * 16 + j];
        }
        float mu  = s * (1.0f / (float)D_DIM);
        float var = q * (1.0f / (float)D_DIM) - mu * mu;
        sMu[tid]            = mu;
        sMu[TOK_TILE + tid] = rsqrtf(var + EPS);
    }
    __syncthreads();

    // ===================== down = relu(rstd*(G - mu*C1) + C2) -> sX buffer 0 =====================
    float* sDown = smem + SX_OFF(0);
    #pragma unroll
    for (int nt = 0; nt < 4; nt++)
        #pragma unroll
        for (int i = 0; i < 4; i++) {
            int t = mg * 16 + (lane >> 2) + ((i >> 1) << 3);
            int r = ng * 32 + nt * 8 + 2 * (lane & 3) + (i & 1);
            float dv = sMu[TOK_TILE + t] * (acc[nt][i] - sMu[t] * g_C1[r]) + g_C2[r];
            sDown[swzf(t, r)] = fmaxf(dv, 0.f);
        }
    __syncthreads();   // scratch dead; wu staging may overwrite sW area

    auto stage2 = [&](int c, int b) {
        const uint32_t wb = sbase + SW_OFF(b) * 4;
        #pragma unroll
        for (int i = 0; i < 4; i++)
            CPA16(wb + xdst[i], wug + (size_t)(c * DC + xt[i]) * (R_DIM / 4) + xc4[i]);
        CPC();
    };

    // ===================== Pass 2: up = down @ w_up^T; out = x + scale*(up + b_up) =====================
    stage2(0, 0); stage2(1, 1); stage2(2, 2);

    for (int c = 0; c < NCHUNK; c++) {
        const int b = c % NSTAGE;
        cpw_tail(c);
        __syncthreads();

        const float* bW = smem + SW_OFF(b);

        float a2[4][4];
        #pragma unroll
        for (int nt = 0; nt < 4; nt++)
            #pragma unroll
            for (int i = 0; i < 4; i++) a2[nt][i] = 0.f;

        #pragma unroll
        for (int ks = 0; ks < 8; ks++) {
            int kb = ks * 8 + (lane & 3);
            unsigned a[4];
            a[0] = __float_as_uint(sDown[swzf(tr0,     kb)]);
            a[1] = __float_as_uint(sDown[swzf(tr0 + 8, kb)]);
            a[2] = __float_as_uint(sDown[swzf(tr0,     kb + 4)]);
            a[3] = __float_as_uint(sDown[swzf(tr0 + 8, kb + 4)]);
            #pragma unroll
            for (int nt = 0; nt < 4; nt++) {
                int n = ng * 32 + nt * 8 + (lane >> 2);
                unsigned bb[2];
                bb[0] = __float_as_uint(bW[swzf(n, kb)]);
                bb[1] = __float_as_uint(bW[swzf(n, kb + 4)]);
                mma_tf32(a2[nt], a, bb);
            }
        }
        __syncthreads();            // done with bW
        if (c + NSTAGE < NCHUNK) stage2(c + NSTAGE, b);

        // epilogue: out = x + scale*(up + b_up)
        #pragma unroll
        for (int nt = 0; nt < 4; nt++) {
            int dl = ng * 32 + nt * 8 + 2 * (lane & 3);
            int d  = c * DC + dl;
            float2 bu = *reinterpret_cast<const float2*>(b_up + d);
            int trow = t0 + mg * 16 + (lane >> 2);

            float2 xv0 = *reinterpret_cast<const float2*>(x + (size_t)trow * D_DIM + d);
            float2 o0;
            o0.x = xv0.x + scaleV * (a2[nt][0] + bu.x);
            o0.y = xv0.y + scaleV * (a2[nt][1] + bu.y);
            *reinterpret_cast<float2*>(out + (size_t)trow * D_DIM + d) = o0;

            float2 xv8 = *reinterpret_cast<const float2*>(x + (size_t)(trow + 8) * D_DIM + d);
            float2 o8;
            o8.x = xv8.x + scaleV * (a2[nt][2] + bu.x);
            o8.y = xv8.y + scaleV * (a2[nt][3] + bu.y);
            *reinterpret_cast<float2*>(out + (size_t)(trow + 8) * D_DIM + d) = o8;
        }
    }
}

// ---------------- launch ----------------

extern "C" void kernel_launch(void* const* d_in, const int* in_sizes, int n_in,
                              void* d_out, int out_size) {
    const float* x      = (const float*)d_in[0];
    const float* gamma  = (const float*)d_in[1];
    const float* beta   = (const float*)d_in[2];
    const float* w_down = (const float*)d_in[3];
    const float* b_down = (const float*)d_in[4];
    const float* w_up   = (const float*)d_in[5];
    const float* b_up   = (const float*)d_in[6];
    const float* scale  = (const float*)d_in[7];
    float* out          = (float*)d_out;

    cudaFuncSetAttribute(adapter_main, cudaFuncAttributeMaxDynamicSharedMemorySize, SMEM_BYTES);

    prep_kernel<<<R_DIM, 256>>>(w_down, gamma, beta, b_down);
    adapter_main<<<N_TOK / TOK_TILE, THREADS, SMEM_BYTES>>>(x, w_up, b_up, scale, out);
}

// round 8
// speedup vs baseline: 1.5684x; 1.5684x over previous
#include <cuda_runtime.h>
#include <cuda_bf16.h>
#include <cstdint>

// x [4,4096,2048] fp32 -> out fp32. R=64.
#define N_TOK    16384
#define D_DIM    2048
#define R_DIM    64
#define TOK_TILE 128
#define NCHUNK   32          // 64-wide chunks over D
#define THREADS  512
#define EPS      1e-5f

// smem byte layout
#define SA_OFF(b) ((b) * 16384)             // 2 x [128 tok x 64 bf16] (x chunk)
#define SB_OFF(b) (32768 + (b) * 8192)      // 4 x [64 x 64 bf16] (weight stages)
#define SDOWN     65536                     // [128 tok x 64 r bf16]
#define SMU       81920                     // 128 f32
#define SRS       82432                     // 128 f32
#define SC1       82944                     // 64 f32
#define SC2       83200                     // 64 f32
#define SMEM_BYTES 83456

__device__ float g_C1[R_DIM];                               // sum_d bf16(gamma*w_down)
__device__ float g_C2[R_DIM];                               // sum_d beta*w_down + b_down
__device__ __nv_bfloat16 g_gw[(size_t)R_DIM * D_DIM];       // bf16(gamma*w_down) [r][d]
__device__ __nv_bfloat16 g_wu[(size_t)D_DIM * R_DIM];       // bf16(w_up) [d][r]

// ---------------- helpers ----------------

// byte offset for (row, 16B-colblock) in a 128B-row SW128 tile
__device__ __forceinline__ uint32_t swz_rc(uint32_t row, uint32_t cb) {
    return row * 128u + ((cb ^ (row & 7u)) << 4);
}
__device__ __forceinline__ uint32_t cvt2(float lo, float hi) {
    uint32_t u;
    asm("cvt.rn.bf16x2.f32 %0, %1, %2;" : "=r"(u) : "f"(hi), "f"(lo));
    return u;
}
__device__ __forceinline__ void ldsm4(uint32_t addr, uint32_t& r0, uint32_t& r1,
                                      uint32_t& r2, uint32_t& r3) {
    asm volatile("ldmatrix.sync.aligned.m8n8.x4.shared.b16 {%0,%1,%2,%3}, [%4];"
        : "=r"(r0), "=r"(r1), "=r"(r2), "=r"(r3) : "r"(addr));
}
__device__ __forceinline__ void mma_bf16(float* c, const uint32_t* a,
                                         uint32_t b0, uint32_t b1) {
    asm volatile(
        "mma.sync.aligned.m16n8k16.row.col.f32.bf16.bf16.f32 "
        "{%0,%1,%2,%3}, {%4,%5,%6,%7}, {%8,%9}, {%0,%1,%2,%3};"
        : "+f"(c[0]), "+f"(c[1]), "+f"(c[2]), "+f"(c[3])
        : "r"(a[0]), "r"(a[1]), "r"(a[2]), "r"(a[3]), "r"(b0), "r"(b1));
}

#define CPA16(dst_u32, src_ptr) \
    asm volatile("cp.async.cg.shared.global [%0], [%1], 16;" :: "r"(dst_u32), "l"(src_ptr))
#define CPC() asm volatile("cp.async.commit_group;")

__device__ __forceinline__ void cpw_tail(int c) {
    if (c < NCHUNK - 2)       asm volatile("cp.async.wait_group 2;");
    else if (c == NCHUNK - 2) asm volatile("cp.async.wait_group 1;");
    else                      asm volatile("cp.async.wait_group 0;");
}

// ---------------- prep: bf16 weights + C1, C2 ----------------

__global__ void prep_kernel(const float* __restrict__ w_down,
                            const float* __restrict__ gamma,
                            const float* __restrict__ beta,
                            const float* __restrict__ b_down,
                            const float* __restrict__ w_up) {
    __shared__ float red1[8], red2[8];
    int r = blockIdx.x;
    float s1 = 0.f, s2 = 0.f;
    for (int d = threadIdx.x; d < D_DIM; d += 256) {
        float w = w_down[r * D_DIM + d];
        __nv_bfloat16 bf = __float2bfloat16(gamma[d] * w);
        g_gw[(size_t)r * D_DIM + d] = bf;
        s1 += __bfloat162float(bf);
        s2 += beta[d] * w;
    }
    // convert w_up rows [r*32, r*32+32)
    for (int i = threadIdx.x; i < 32 * R_DIM; i += 256) {
        int idx = r * 32 * R_DIM + i;
        g_wu[idx] = __float2bfloat16(w_up[idx]);
    }
    #pragma unroll
    for (int o = 16; o; o >>= 1) {
        s1 += __shfl_down_sync(0xFFFFFFFFu, s1, o);
        s2 += __shfl_down_sync(0xFFFFFFFFu, s2, o);
    }
    if ((threadIdx.x & 31) == 0) { red1[threadIdx.x >> 5] = s1; red2[threadIdx.x >> 5] = s2; }
    __syncthreads();
    if (threadIdx.x == 0) {
        float t1 = 0.f, t2 = 0.f;
        #pragma unroll
        for (int i = 0; i < 8; i++) { t1 += red1[i]; t2 += red2[i]; }
        g_C1[r] = t1;
        g_C2[r] = t2 + b_down[r];
    }
}

// ---------------- main fused kernel ----------------

__global__ __launch_bounds__(THREADS, 1) void adapter_main(
    const float* __restrict__ x,
    const float* __restrict__ b_up,
    const float* __restrict__ scale,
    float* __restrict__ out)
{
    extern __shared__ char smc[];
    const uint32_t sb = (uint32_t)__cvta_generic_to_shared(smc);
    float* smf = reinterpret_cast<float*>(smc);

    const int tid  = threadIdx.x;
    const int lane = tid & 31;
    const int wrp  = tid >> 5;       // 0..15
    const int mg   = wrp & 7;        // 16-token m-strip
    const int ng   = wrp >> 3;       // 32-col n-strip
    const int t0   = blockIdx.x * TOK_TILE;
    const int tok  = tid >> 2;       // 0..127: this thread's stats token
    const float scaleV = scale[0];

    if (tid < 64) {
        smf[SC1 / 4 + tid] = g_C1[tid];
        smf[SC2 / 4 + tid] = g_C2[tid];
    }

    // x loads: row (t0+tok), per chunk c: 4 float4 at c*16 + (tid&3)*4
    const float4* xr4 = reinterpret_cast<const float4*>(x) +
                        (size_t)(t0 + tok) * (D_DIM / 4) + (tid & 3) * 4;
    // bf16 STS targets into sA (row tok, colblocks (tid&3)*2, +1)
    const uint32_t stsA0 = swz_rc(tok, (tid & 3) * 2);
    const uint32_t stsA1 = swz_rc(tok, (tid & 3) * 2 + 1);
    // weight staging: 16B per thread
    const int grow = tid >> 3, gcb = tid & 7;
    const __nv_bfloat16* gwsrc = g_gw + (size_t)grow * D_DIM + gcb * 8;
    const __nv_bfloat16* wusrc = g_wu + (size_t)grow * R_DIM + gcb * 8;
    const uint32_t gdst = swz_rc(grow, gcb);

    // ldmatrix coords
    const uint32_t aRow  = mg * 16 + (lane & 15);
    const uint32_t aKs   = lane >> 4;                               // 0/1
    const uint32_t bRow0 = ng * 32 + (lane & 7) + ((lane >> 4) << 3);
    const uint32_t bKs   = (lane >> 3) & 1;

    float acc[4][4];
    #pragma unroll
    for (int nt = 0; nt < 4; nt++)
        #pragma unroll
        for (int i = 0; i < 4; i++) acc[nt][i] = 0.f;

    float sum = 0.f, sq = 0.f;
    float4 xa[4], xb[4];

    auto stage_gw = [&](int c) {
        CPA16(sb + SB_OFF((unsigned)c & 3) + gdst, gwsrc + c * 64);
        CPC();
    };
    auto stage_wu = [&](int c) {
        CPA16(sb + SB_OFF((unsigned)c & 3) + gdst, wusrc + (size_t)c * 64 * R_DIM);
        CPC();
    };
    auto ldgx = [&](int c, float4 (&v)[4]) {
        #pragma unroll
        for (int j = 0; j < 4; j++) v[j] = xr4[c * 16 + j];
    };
    auto cvt_sts = [&](int k, float4 (&v)[4]) {
        uint32_t base = sb + SA_OFF(k & 1);
        uint32_t p[8];
        #pragma unroll
        for (int j = 0; j < 4; j++) {
            sum += v[j].x + v[j].y + v[j].z + v[j].w;
            sq  += v[j].x * v[j].x + v[j].y * v[j].y + v[j].z * v[j].z + v[j].w * v[j].w;
            p[2 * j]     = cvt2(v[j].x, v[j].y);
            p[2 * j + 1] = cvt2(v[j].z, v[j].w);
        }
        asm volatile("st.shared.v4.b32 [%0], {%1,%2,%3,%4};"
            :: "r"(base + stsA0), "r"(p[0]), "r"(p[1]), "r"(p[2]), "r"(p[3]));
        asm volatile("st.shared.v4.b32 [%0], {%1,%2,%3,%4};"
            :: "r"(base + stsA1), "r"(p[4]), "r"(p[5]), "r"(p[6]), "r"(p[7]));
    };

    auto pass1_iter = [&](int c, float4 (&curN)[4], float4 (&nxt)[4]) {
        cpw_tail(c);
        __syncthreads();
        if (c + 3 < NCHUNK) stage_gw(c + 3);
        if (c + 2 < NCHUNK) ldgx(c + 2, nxt);
        if (c + 1 < NCHUNK) cvt_sts(c + 1, curN);
        const uint32_t abase = sb + SA_OFF(c & 1);
        const uint32_t bbase = sb + SB_OFF((unsigned)c & 3);
        #pragma unroll
        for (int ks = 0; ks < 4; ks++) {
            uint32_t a[4];
            ldsm4(abase + swz_rc(aRow, ks * 2 + aKs), a[0], a[1], a[2], a[3]);
            uint32_t b0[4], b1[4];
            ldsm4(bbase + swz_rc(bRow0,      ks * 2 + bKs), b0[0], b0[1], b0[2], b0[3]);
            ldsm4(bbase + swz_rc(bRow0 + 16, ks * 2 + bKs), b1[0], b1[1], b1[2], b1[3]);
            mma_bf16(acc[0], a, b0[0], b0[1]);
            mma_bf16(acc[1], a, b0[2], b0[3]);
            mma_bf16(acc[2], a, b1[0], b1[1]);
            mma_bf16(acc[3], a, b1[2], b1[3]);
        }
    };

    // ---- pass-1 prologue ----
    ldgx(0, xa);
    stage_gw(0); stage_gw(1); stage_gw(2);
    cvt_sts(0, xa);
    ldgx(1, xb);

    // ---- pass 1: stats + G = x @ gw^T ----
    for (int c = 0; c < NCHUNK; c += 2) {
        pass1_iter(c,     xb, xa);   // even chunk: c+1 lives in xb, LDG c+2 -> xa
        pass1_iter(c + 1, xa, xb);
    }

    // ---- stats finalize (quad shuffle) ----
    sum += __shfl_xor_sync(0xFFFFFFFFu, sum, 1);
    sum += __shfl_xor_sync(0xFFFFFFFFu, sum, 2);
    sq  += __shfl_xor_sync(0xFFFFFFFFu, sq, 1);
    sq  += __shfl_xor_sync(0xFFFFFFFFu, sq, 2);
    if ((tid & 3) == 0) {
        float mu  = sum * (1.0f / (float)D_DIM);
        float var = sq * (1.0f / (float)D_DIM) - mu * mu;
        smf[SMU / 4 + tok] = mu;
        smf[SRS / 4 + tok] = rsqrtf(var + EPS);
    }
    __syncthreads();

    // ---- down = relu(rstd*(G - mu*C1) + C2) -> sDown (bf16, SW128) ----
    {
        const float* sC1f = smf + SC1 / 4;
        const float* sC2f = smf + SC2 / 4;
        const float* sMuF = smf + SMU / 4;
        const float* sRsF = smf + SRS / 4;
        #pragma unroll
        for (int nt = 0; nt < 4; nt++) {
            int r = ng * 32 + nt * 8 + 2 * (lane & 3);
            float c1a = sC1f[r], c1b = sC1f[r + 1];
            float c2a = sC2f[r], c2b = sC2f[r + 1];
            #pragma unroll
            for (int ip = 0; ip < 2; ip++) {
                int t = mg * 16 + (lane >> 2) + ip * 8;
                float mu = sMuF[t], rs = sRsF[t];
                float d0 = fmaxf(rs * (acc[nt][ip * 2]     - mu * c1a) + c2a, 0.f);
                float d1 = fmaxf(rs * (acc[nt][ip * 2 + 1] - mu * c1b) + c2b, 0.f);
                uint32_t u = cvt2(d0, d1);
                uint32_t off = (uint32_t)t * 128 + ((((uint32_t)r >> 3) ^ (t & 7)) << 4) +
                               (((uint32_t)r * 2) & 15);
                *reinterpret_cast<uint32_t*>(smc + SDOWN + off) = u;
            }
        }
    }
    __syncthreads();

    // ---- pass-2 A fragments (persistent) ----
    uint32_t af[4][4];
    #pragma unroll
    for (int ks = 0; ks < 4; ks++)
        ldsm4(sb + SDOWN + swz_rc(aRow, ks * 2 + aKs),
              af[ks][0], af[ks][1], af[ks][2], af[ks][3]);

    // ---- pass 2: up = down @ w_up^T; out = x + scale*(up + b_up) ----
    stage_wu(0); stage_wu(1); stage_wu(2);

    for (int c = 0; c < NCHUNK; c++) {
        cpw_tail(c);
        __syncthreads();
        if (c + 3 < NCHUNK) stage_wu(c + 3);

        float a2[4][4];
        #pragma unroll
        for (int nt = 0; nt < 4; nt++)
            #pragma unroll
            for (int i = 0; i < 4; i++) a2[nt][i] = 0.f;

        const uint32_t bbase = sb + SB_OFF((unsigned)c & 3);
        #pragma unroll
        for (int ks = 0; ks < 4; ks++) {
            uint32_t b0[4], b1[4];
            ldsm4(bbase + swz_rc(bRow0,      ks * 2 + bKs), b0[0], b0[1], b0[2], b0[3]);
            ldsm4(bbase + swz_rc(bRow0 + 16, ks * 2 + bKs), b1[0], b1[1], b1[2], b1[3]);
            mma_bf16(a2[0], af[ks], b0[0], b0[1]);
            mma_bf16(a2[1], af[ks], b0[2], b0[3]);
            mma_bf16(a2[2], af[ks], b1[0], b1[1]);
            mma_bf16(a2[3], af[ks], b1[2], b1[3]);
        }

        // epilogue
        #pragma unroll
        for (int nt = 0; nt < 4; nt++) {
            int dl = ng * 32 + nt * 8 + 2 * (lane & 3);
            int d  = c * 64 + dl;
            float2 bu = *reinterpret_cast<const float2*>(b_up + d);
            #pragma unroll
            for (int ip = 0; ip < 2; ip++) {
                int trow = t0 + mg * 16 + (lane >> 2) + ip * 8;
                float2 xv = *reinterpret_cast<const float2*>(x + (size_t)trow * D_DIM + d);
                float2 o;
                o.x = xv.x + scaleV * (a2[nt][ip * 2]     + bu.x);
                o.y = xv.y + scaleV * (a2[nt][ip * 2 + 1] + bu.y);
                *reinterpret_cast<float2*>(out + (size_t)trow * D_DIM + d) = o;
            }
        }
    }
}

// ---------------- launch ----------------

extern "C" void kernel_launch(void* const* d_in, const int* in_sizes, int n_in,
                              void* d_out, int out_size) {
    const float* x      = (const float*)d_in[0];
    const float* gamma  = (const float*)d_in[1];
    const float* beta   = (const float*)d_in[2];
    const float* w_down = (const float*)d_in[3];
    const float* b_down = (const float*)d_in[4];
    const float* w_up   = (const float*)d_in[5];
    const float* b_up   = (const float*)d_in[6];
    const float* scale  = (const float*)d_in[7];
    float* out          = (float*)d_out;

    cudaFuncSetAttribute(adapter_main, cudaFuncAttributeMaxDynamicSharedMemorySize, SMEM_BYTES);

    prep_kernel<<<R_DIM, 256>>>(w_down, gamma, beta, b_down, w_up);
    adapter_main<<<N_TOK / TOK_TILE, THREADS, SMEM_BYTES>>>(x, b_up, scale, out);
}